// round 2
// baseline (speedup 1.0000x reference)
#include <cuda_runtime.h>
#include <math.h>

#define BB 2
#define TT 2048
#define DIMN 1024
#define HEADS 16
#define DH 64
#define INNER 1024
#define RR 8
#define NT (BB*TT)            /* 4096 tokens */
#define LORA_SCALE 0.25f
#define EPS_LN 1e-5f

// ---------------- scratch (static device allocations; no cudaMalloc) -------
__device__ float g_xn[NT*DIMN];
__device__ float g_mn[NT*DIMN];
__device__ float g_q[NT*INNER];
__device__ float g_k[NT*INNER];
__device__ float g_v[NT*INNER];
__device__ float g_ao[NT*INNER];
__device__ float g_low[3*NT*RR];     // scaled (A x)*(G m)*alpha/r for q,k,v
__device__ float g_gateo[NT*RR];     // raw (Go m)
__device__ float g_lowo[NT*RR];      // scaled (Ao out)*(Go m)*alpha/r

// ---------------- LayerNorm: one block per (token, tensor) -----------------
__global__ void ln_kernel(const float* __restrict__ x, const float* __restrict__ mt,
                          const float* __restrict__ gx, const float* __restrict__ bx,
                          const float* __restrict__ gm, const float* __restrict__ bm)
{
    int t = blockIdx.x;
    int which = blockIdx.y;
    const float* src = (which ? mt : x) + (size_t)t * DIMN;
    float*       dst = (which ? g_mn : g_xn) + (size_t)t * DIMN;
    const float* g = which ? gm : gx;
    const float* b = which ? bm : bx;
    int tid = threadIdx.x;                      // 256 threads, 4 elems each
    float4 v = ((const float4*)src)[tid];
    float s  = v.x + v.y + v.z + v.w;
    float sq = v.x*v.x + v.y*v.y + v.z*v.z + v.w*v.w;
    __shared__ float red[2][8];
    #pragma unroll
    for (int m = 16; m; m >>= 1) {
        s  += __shfl_xor_sync(~0u, s, m);
        sq += __shfl_xor_sync(~0u, sq, m);
    }
    int w = tid >> 5, l = tid & 31;
    if (l == 0) { red[0][w] = s; red[1][w] = sq; }
    __syncthreads();
    if (w == 0) {
        float s2 = (l < 8) ? red[0][l] : 0.f;
        float q2 = (l < 8) ? red[1][l] : 0.f;
        #pragma unroll
        for (int m = 4; m; m >>= 1) {
            s2 += __shfl_xor_sync(~0u, s2, m);
            q2 += __shfl_xor_sync(~0u, q2, m);
        }
        if (l == 0) { red[0][0] = s2; red[1][0] = q2; }
    }
    __syncthreads();
    s = red[0][0]; sq = red[1][0];
    float mean = s * (1.f / DIMN);
    float var  = sq * (1.f / DIMN) - mean * mean;
    float rstd = rsqrtf(var + EPS_LN);
    float4 gv = ((const float4*)g)[tid];
    float4 bv = ((const float4*)b)[tid];
    float4 o;
    o.x = (v.x - mean) * rstd * gv.x + bv.x;
    o.y = (v.y - mean) * rstd * gv.y + bv.y;
    o.z = (v.z - mean) * rstd * gv.z + bv.z;
    o.w = (v.w - mean) * rstd * gv.w + bv.w;
    ((float4*)dst)[tid] = o;
}

// ---------------- per-token rank-8 dots: gates + q/k/v lows ----------------
// 8 warps per block, one token per warp. 56 dot products of length 1024.
__global__ void dots_kernel(const float* __restrict__ Gq, const float* __restrict__ Gk,
                            const float* __restrict__ Gv, const float* __restrict__ Go,
                            const float* __restrict__ Aq, const float* __restrict__ Ak,
                            const float* __restrict__ Av)
{
    int tid = threadIdx.x;
    int w = tid >> 5, lane = tid & 31;
    int tok = blockIdx.x * 8 + w;
    const float4* x4 = (const float4*)(g_xn + (size_t)tok * DIMN);
    const float4* m4 = (const float4*)(g_mn + (size_t)tok * DIMN);
    __shared__ float stage[8][56];
    for (int o = 0; o < 56; o++) {
        const float4* w4;
        const float4* s4;
        if (o < 32) {
            int p = o >> 3, r = o & 7;
            const float* G = (p == 0) ? Gq : (p == 1) ? Gk : (p == 2) ? Gv : Go;
            w4 = (const float4*)(G + (size_t)r * DIMN);
            s4 = m4;
        } else {
            int oo = o - 32; int p = oo >> 3, r = oo & 7;
            const float* A = (p == 0) ? Aq : (p == 1) ? Ak : Av;
            w4 = (const float4*)(A + (size_t)r * DIMN);
            s4 = x4;
        }
        float acc = 0.f;
        #pragma unroll
        for (int k = lane; k < DIMN / 4; k += 32) {
            float4 a = s4[k], c = w4[k];
            acc += a.x*c.x + a.y*c.y + a.z*c.z + a.w*c.w;
        }
        #pragma unroll
        for (int m = 16; m; m >>= 1) acc += __shfl_xor_sync(~0u, acc, m);
        if (lane == 0) stage[w][o] = acc;
    }
    __syncwarp();
    if (lane < 8) {
        int r = lane;
        g_gateo[(size_t)tok * RR + r] = stage[w][24 + r];          // Go gate (raw)
        #pragma unroll
        for (int p = 0; p < 3; p++) {
            float gate = stage[w][p * 8 + r];
            float lowr = stage[w][32 + p * 8 + r];
            g_low[((size_t)p * NT + tok) * RR + r] = lowr * gate * LORA_SCALE;
        }
    }
}

// ---------------- rank-8 dots for output projection ------------------------
__global__ void lowo_kernel(const float* __restrict__ Ao)
{
    int tid = threadIdx.x;
    int w = tid >> 5, lane = tid & 31;
    int tok = blockIdx.x * 8 + w;
    const float4* a4 = (const float4*)(g_ao + (size_t)tok * INNER);
    for (int r = 0; r < RR; r++) {
        const float4* w4 = (const float4*)(Ao + (size_t)r * INNER);
        float acc = 0.f;
        #pragma unroll
        for (int k = lane; k < INNER / 4; k += 32) {
            float4 a = a4[k], c = w4[k];
            acc += a.x*c.x + a.y*c.y + a.z*c.z + a.w*c.w;
        }
        #pragma unroll
        for (int m = 16; m; m >>= 1) acc += __shfl_xor_sync(~0u, acc, m);
        if (lane == 0)
            g_lowo[(size_t)tok * RR + r] = acc * g_gateo[(size_t)tok * RR + r] * LORA_SCALE;
    }
}

// ---------------- fused GEMM: C = X @ W^T + low @ Bm^T ---------------------
// X [4096,1024] row-major, W [1024(out),1024(k)] row-major, low [4096,8],
// Bm [1024(out),8]. 128x128 tile, BK=8, 8x8 per thread, 256 threads.
__global__ __launch_bounds__(256, 2)
void gemm_kernel(const float* __restrict__ X, const float* __restrict__ W,
                 const float* __restrict__ low, const float* __restrict__ Bm,
                 float* __restrict__ C)
{
    __shared__ float As[8][128];
    __shared__ float Bs[8][128];
    int tid = threadIdx.x;
    int tx = tid & 15, ty = tid >> 4;
    int m0 = blockIdx.y * 128, n0 = blockIdx.x * 128;
    float acc[8][8];
    #pragma unroll
    for (int i = 0; i < 8; i++)
        #pragma unroll
        for (int j = 0; j < 8; j++) acc[i][j] = 0.f;

    int lrow = tid >> 1;
    int lk   = (tid & 1) * 4;
    const float* Xp = X + (size_t)(m0 + lrow) * DIMN + lk;
    const float* Wp = W + (size_t)(n0 + lrow) * DIMN + lk;

    for (int k0 = 0; k0 < DIMN; k0 += 8) {
        float4 av = *(const float4*)(Xp + k0);
        float4 bv = *(const float4*)(Wp + k0);
        __syncthreads();
        As[lk + 0][lrow] = av.x; As[lk + 1][lrow] = av.y;
        As[lk + 2][lrow] = av.z; As[lk + 3][lrow] = av.w;
        Bs[lk + 0][lrow] = bv.x; Bs[lk + 1][lrow] = bv.y;
        Bs[lk + 2][lrow] = bv.z; Bs[lk + 3][lrow] = bv.w;
        __syncthreads();
        #pragma unroll
        for (int k = 0; k < 8; k++) {
            float a[8], b[8];
            *(float4*)(a)     = *(const float4*)&As[k][ty * 8];
            *(float4*)(a + 4) = *(const float4*)&As[k][ty * 8 + 4];
            *(float4*)(b)     = *(const float4*)&Bs[k][tx * 8];
            *(float4*)(b + 4) = *(const float4*)&Bs[k][tx * 8 + 4];
            #pragma unroll
            for (int i = 0; i < 8; i++)
                #pragma unroll
                for (int j = 0; j < 8; j++) acc[i][j] += a[i] * b[j];
        }
    }
    // fused rank-8 LoRA epilogue
    #pragma unroll
    for (int i = 0; i < 8; i++) {
        int m = m0 + ty * 8 + i;
        const float* lp = low + (size_t)m * RR;
        float lw[8];
        *(float4*)(lw)     = *(const float4*)(lp);
        *(float4*)(lw + 4) = *(const float4*)(lp + 4);
        #pragma unroll
        for (int j = 0; j < 8; j++) {
            int n = n0 + tx * 8 + j;
            const float* bp = Bm + (size_t)n * RR;
            float add = 0.f;
            #pragma unroll
            for (int r = 0; r < 8; r++) add += lw[r] * bp[r];
            acc[i][j] += add;
        }
    }
    #pragma unroll
    for (int i = 0; i < 8; i++) {
        int m = m0 + ty * 8 + i;
        float* cp = C + (size_t)m * DIMN + n0 + tx * 8;
        *(float4*)(cp)     = make_float4(acc[i][0], acc[i][1], acc[i][2], acc[i][3]);
        *(float4*)(cp + 4) = make_float4(acc[i][4], acc[i][5], acc[i][6], acc[i][7]);
    }
}

// ---------------- flash attention, block-causal over 256-frames ------------
// BQ=64, BKV=32, DH=64. Grid (32 qtiles, 16 heads, 2 batch), 256 threads.
// No mask math: kv loop bound = (frame(q)+1)*256. P tile reuses K smem.
__global__ __launch_bounds__(256)
void attn_kernel()
{
    __shared__ float Qs[64 * 64];
    __shared__ float Ks[32 * 68];     // 2176 floats; reused as P[64*32]
    __shared__ float Vs[32 * 64];
    int tid = threadIdx.x;
    int qt = blockIdx.x, h = blockIdx.y, b = blockIdx.z;
    int q0 = qt * 64;
    const float* qbase = g_q + ((size_t)(b * TT + q0)) * INNER + h * DH;
    #pragma unroll
    for (int i = 0; i < 4; i++) {
        int idx = tid + i * 256;
        int row = idx >> 4, d4 = (idx & 15) * 4;
        *(float4*)&Qs[row * 64 + d4] = *(const float4*)(qbase + (size_t)row * INNER + d4);
    }
    int tx = tid & 7, ty = tid >> 3;          // tx: 8 col-groups, ty: 32 row-groups
    int r0 = ty * 2, c0 = tx * 4, d0 = tx * 8;
    float m_i[2] = {-1e30f, -1e30f};
    float l_i[2] = {0.f, 0.f};
    float o[2][8];
    #pragma unroll
    for (int i = 0; i < 2; i++)
        #pragma unroll
        for (int j = 0; j < 8; j++) o[i][j] = 0.f;

    int nkv = (qt / 4 + 1) * 8;               // 32-wide kv chunks allowed
    const float* kbase0 = g_k + (size_t)(b * TT) * INNER + h * DH;
    const float* vbase0 = g_v + (size_t)(b * TT) * INNER + h * DH;

    for (int kb = 0; kb < nkv; kb++) {
        const float* kp = kbase0 + (size_t)(kb * 32) * INNER;
        const float* vp = vbase0 + (size_t)(kb * 32) * INNER;
        float4 kr[2], vr[2];
        #pragma unroll
        for (int i = 0; i < 2; i++) {
            int idx = tid + i * 256;
            int row = idx >> 4, d4 = (idx & 15) * 4;
            kr[i] = *(const float4*)(kp + (size_t)row * INNER + d4);
            vr[i] = *(const float4*)(vp + (size_t)row * INNER + d4);
        }
        __syncthreads();                       // prev iter done with Ks(P)/Vs
        #pragma unroll
        for (int i = 0; i < 2; i++) {
            int idx = tid + i * 256;
            int row = idx >> 4, d4 = (idx & 15) * 4;
            *(float4*)&Ks[row * 68 + d4] = kr[i];
            *(float4*)&Vs[row * 64 + d4] = vr[i];
        }
        __syncthreads();

        float s[2][4] = {{0.f,0.f,0.f,0.f},{0.f,0.f,0.f,0.f}};
        #pragma unroll
        for (int d = 0; d < 64; d += 4) {
            float4 q0v = *(const float4*)&Qs[(r0 + 0) * 64 + d];
            float4 q1v = *(const float4*)&Qs[(r0 + 1) * 64 + d];
            #pragma unroll
            for (int j = 0; j < 4; j++) {
                float4 kv = *(const float4*)&Ks[(c0 + j) * 68 + d];
                s[0][j] += q0v.x*kv.x + q0v.y*kv.y + q0v.z*kv.z + q0v.w*kv.w;
                s[1][j] += q1v.x*kv.x + q1v.y*kv.y + q1v.z*kv.z + q1v.w*kv.w;
            }
        }
        #pragma unroll
        for (int i = 0; i < 2; i++) {
            float mx = -1e30f;
            #pragma unroll
            for (int j = 0; j < 4; j++) { s[i][j] *= 0.125f; mx = fmaxf(mx, s[i][j]); }
            #pragma unroll
            for (int mm = 4; mm; mm >>= 1) mx = fmaxf(mx, __shfl_xor_sync(~0u, mx, mm));
            float mnew  = fmaxf(m_i[i], mx);
            float alpha = __expf(m_i[i] - mnew);
            float rs = 0.f;
            #pragma unroll
            for (int j = 0; j < 4; j++) { float p = __expf(s[i][j] - mnew); s[i][j] = p; rs += p; }
            #pragma unroll
            for (int mm = 4; mm; mm >>= 1) rs += __shfl_xor_sync(~0u, rs, mm);
            l_i[i] = l_i[i] * alpha + rs;
            m_i[i] = mnew;
            #pragma unroll
            for (int j = 0; j < 8; j++) o[i][j] *= alpha;
        }
        __syncthreads();                       // everyone done reading Ks
        float* Ps = Ks;                        // reuse K smem as P [64 x 32]
        *(float4*)&Ps[(r0 + 0) * 32 + c0] = *(float4*)&s[0][0];
        *(float4*)&Ps[(r0 + 1) * 32 + c0] = *(float4*)&s[1][0];
        __syncthreads();
        #pragma unroll 8
        for (int kc = 0; kc < 32; kc++) {
            float4 v0 = *(const float4*)&Vs[kc * 64 + d0];
            float4 v1 = *(const float4*)&Vs[kc * 64 + d0 + 4];
            float p0 = Ps[(r0 + 0) * 32 + kc];
            float p1 = Ps[(r0 + 1) * 32 + kc];
            o[0][0] += p0 * v0.x; o[0][1] += p0 * v0.y; o[0][2] += p0 * v0.z; o[0][3] += p0 * v0.w;
            o[0][4] += p0 * v1.x; o[0][5] += p0 * v1.y; o[0][6] += p0 * v1.z; o[0][7] += p0 * v1.w;
            o[1][0] += p1 * v0.x; o[1][1] += p1 * v0.y; o[1][2] += p1 * v0.z; o[1][3] += p1 * v0.w;
            o[1][4] += p1 * v1.x; o[1][5] += p1 * v1.y; o[1][6] += p1 * v1.z; o[1][7] += p1 * v1.w;
        }
    }
    float* obase = g_ao + ((size_t)(b * TT + q0)) * INNER + h * DH;
    #pragma unroll
    for (int i = 0; i < 2; i++) {
        float inv = 1.f / l_i[i];
        *(float4*)(obase + (size_t)(r0 + i) * INNER + d0) =
            make_float4(o[i][0] * inv, o[i][1] * inv, o[i][2] * inv, o[i][3] * inv);
        *(float4*)(obase + (size_t)(r0 + i) * INNER + d0 + 4) =
            make_float4(o[i][4] * inv, o[i][5] * inv, o[i][6] * inv, o[i][7] * inv);
    }
}

// ---------------- launch ---------------------------------------------------
extern "C" void kernel_launch(void* const* d_in, const int* in_sizes, int n_in,
                              void* d_out, int out_size)
{
    const float* x  = (const float*)d_in[0];
    const float* mt = (const float*)d_in[1];
    const float* ng = (const float*)d_in[2];
    const float* nb = (const float*)d_in[3];
    const float* mg = (const float*)d_in[4];
    const float* mb = (const float*)d_in[5];
    const float* Wq = (const float*)d_in[6];
    const float* Aq = (const float*)d_in[7];
    const float* Bq = (const float*)d_in[8];
    const float* Gq = (const float*)d_in[9];
    const float* Wk = (const float*)d_in[10];
    const float* Ak = (const float*)d_in[11];
    const float* Bk = (const float*)d_in[12];
    const float* Gk = (const float*)d_in[13];
    const float* Wv = (const float*)d_in[14];
    const float* Av = (const float*)d_in[15];
    const float* Bv = (const float*)d_in[16];
    const float* Gv = (const float*)d_in[17];
    const float* Wo = (const float*)d_in[18];
    const float* Ao = (const float*)d_in[19];
    const float* Bo = (const float*)d_in[20];
    const float* Go = (const float*)d_in[21];
    float* out = (float*)d_out;

    float *xn, *qb, *kb, *vb, *aob, *lowb, *lowob;
    cudaGetSymbolAddress((void**)&xn,    g_xn);
    cudaGetSymbolAddress((void**)&qb,    g_q);
    cudaGetSymbolAddress((void**)&kb,    g_k);
    cudaGetSymbolAddress((void**)&vb,    g_v);
    cudaGetSymbolAddress((void**)&aob,   g_ao);
    cudaGetSymbolAddress((void**)&lowb,  g_low);
    cudaGetSymbolAddress((void**)&lowob, g_lowo);

    ln_kernel<<<dim3(NT, 2), 256>>>(x, mt, ng, nb, mg, mb);
    dots_kernel<<<NT / 8, 256>>>(Gq, Gk, Gv, Go, Aq, Ak, Av);
    gemm_kernel<<<dim3(8, 32), 256>>>(xn, Wq, lowb + 0 * (size_t)NT * RR, Bq, qb);
    gemm_kernel<<<dim3(8, 32), 256>>>(xn, Wk, lowb + 1 * (size_t)NT * RR, Bk, kb);
    gemm_kernel<<<dim3(8, 32), 256>>>(xn, Wv, lowb + 2 * (size_t)NT * RR, Bv, vb);
    attn_kernel<<<dim3(32, 16, 2), 256>>>();
    lowo_kernel<<<NT / 8, 256>>>(Ao);
    gemm_kernel<<<dim3(8, 32), 256>>>(aob, Wo, lowob, Bo, out);
}

// round 5
// speedup vs baseline: 4.8801x; 4.8801x over previous
#include <cuda_runtime.h>
#include <cuda_bf16.h>
#include <cstdint>
#include <math.h>

#define BB 2
#define TT 2048
#define DIMN 1024
#define HEADS 16
#define DH 64
#define INNER 1024
#define RR 8
#define NT (BB*TT)
#define LORA_SCALE 0.25f
#define EPS_LN 1e-5f

// ---------------- static scratch -------------------------------------------
__device__ float g_xn[NT*DIMN];
__device__ float g_mn[NT*DIMN];
__device__ float g_ao[NT*INNER];
__device__ float g_low[3*NT*RR];
__device__ float g_gateo[NT*RR];
__device__ float g_lowo[NT*RR];
__device__ __nv_bfloat16 g_xhi[NT*DIMN];
__device__ __nv_bfloat16 g_xlo[NT*DIMN];
__device__ __nv_bfloat16 g_whi[DIMN*INNER];
__device__ __nv_bfloat16 g_wlo[DIMN*INNER];
__device__ __nv_bfloat16 g_qhi[NT*INNER];
__device__ __nv_bfloat16 g_qlo[NT*INNER];
__device__ __nv_bfloat16 g_khi[NT*INNER];
__device__ __nv_bfloat16 g_klo[NT*INNER];
__device__ __nv_bfloat16 g_vhi[NT*INNER];
__device__ __nv_bfloat16 g_vlo[NT*INNER];
__device__ __nv_bfloat16 g_aohi[NT*INNER];
__device__ __nv_bfloat16 g_aolo[NT*INNER];

// ---------------- helpers --------------------------------------------------
__device__ __forceinline__ uint32_t smem_u32(const void* p){
    uint32_t a;
    asm("{ .reg .u64 t; cvta.to.shared.u64 t, %1; cvt.u32.u64 %0, t; }" : "=r"(a) : "l"(p));
    return a;
}
#define CP16(sm, g) asm volatile("cp.async.cg.shared.global [%0], [%1], 16;" :: "r"(sm), "l"(g) : "memory")
#define CP_COMMIT() asm volatile("cp.async.commit_group;" ::: "memory")
#define CP_WAIT(n)  asm volatile("cp.async.wait_group %0;" :: "n"(n) : "memory")

__device__ __forceinline__ void ldsm4(uint32_t* r, uint32_t a){
    asm volatile("ldmatrix.sync.aligned.m8n8.x4.shared.b16 {%0,%1,%2,%3}, [%4];"
        : "=r"(r[0]),"=r"(r[1]),"=r"(r[2]),"=r"(r[3]) : "r"(a));
}
__device__ __forceinline__ void ldsm4t(uint32_t* r, uint32_t a){
    asm volatile("ldmatrix.sync.aligned.m8n8.x4.trans.shared.b16 {%0,%1,%2,%3}, [%4];"
        : "=r"(r[0]),"=r"(r[1]),"=r"(r[2]),"=r"(r[3]) : "r"(a));
}
__device__ __forceinline__ void mma_bf16(float* c, const uint32_t* a, uint32_t b0, uint32_t b1){
    asm volatile("mma.sync.aligned.m16n8k16.row.col.f32.bf16.bf16.f32 "
        "{%0,%1,%2,%3}, {%4,%5,%6,%7}, {%8,%9}, {%0,%1,%2,%3};"
        : "+f"(c[0]),"+f"(c[1]),"+f"(c[2]),"+f"(c[3])
        : "r"(a[0]),"r"(a[1]),"r"(a[2]),"r"(a[3]),"r"(b0),"r"(b1));
}
__device__ __forceinline__ void split2(float f0, float f1, uint32_t& hi, uint32_t& lo){
    __nv_bfloat16 h0 = __float2bfloat16_rn(f0);
    __nv_bfloat16 h1 = __float2bfloat16_rn(f1);
    float r0 = f0 - __bfloat162float(h0);
    float r1 = f1 - __bfloat162float(h1);
    __nv_bfloat16 l0 = __float2bfloat16_rn(r0);
    __nv_bfloat16 l1 = __float2bfloat16_rn(r1);
    hi = (uint32_t)__bfloat16_as_ushort(h0) | ((uint32_t)__bfloat16_as_ushort(h1) << 16);
    lo = (uint32_t)__bfloat16_as_ushort(l0) | ((uint32_t)__bfloat16_as_ushort(l1) << 16);
}

// ---------------- fp32 -> bf16 hi/lo split (weights) -----------------------
__global__ void cvt_split(const float4* __restrict__ src, uint2* __restrict__ hi,
                          uint2* __restrict__ lo, int n4)
{
    int i = blockIdx.x * 256 + threadIdx.x;
    if (i >= n4) return;
    float4 v = src[i];
    uint32_t h0, l0, h1, l1;
    split2(v.x, v.y, h0, l0);
    split2(v.z, v.w, h1, l1);
    hi[i] = make_uint2(h0, h1);
    lo[i] = make_uint2(l0, l1);
}

// ======================= HMMA split-bf16 GEMM ==============================
// C[4096,1024] = A@B^T + low@Bm^T.  BM=128, BN=128, BK=64, 3 stages.
#define TPITCH 144          /* 72 b16 per row */
#define TILE_B 18432        /* 128 * 144 */
#define STG_B  (4*TILE_B)   /* 73728 */
#define SM_STG 4096
#define GSMEM  (SM_STG + 3*STG_B)   /* 225280 */

__global__ __launch_bounds__(256, 1)
void gemm_mma(const __nv_bfloat16* __restrict__ Ahi, const __nv_bfloat16* __restrict__ Alo,
              const __nv_bfloat16* __restrict__ Bhi, const __nv_bfloat16* __restrict__ Blo,
              const float* __restrict__ low, const float* __restrict__ Bm,
              __nv_bfloat16* __restrict__ Chi, __nv_bfloat16* __restrict__ Clo,
              float* __restrict__ Cf)
{
    extern __shared__ char smem[];
    uint32_t sbase = smem_u32(smem);
    int tid = threadIdx.x, lane = tid & 31, wid = tid >> 5;
    int wm = wid >> 1, wn = wid & 1;
    int m0 = blockIdx.y * 128, n0 = blockIdx.x * 128;

    ((float4*)smem)[tid] = ((const float4*)(Bm + (size_t)n0 * 8))[tid];

    const char* gb0 = (const char*)(Ahi + (size_t)m0 * DIMN);
    const char* gb1 = (const char*)(Alo + (size_t)m0 * DIMN);
    const char* gb2 = (const char*)(Bhi + (size_t)n0 * DIMN);
    const char* gb3 = (const char*)(Blo + (size_t)n0 * DIMN);

    int lrow[4], lcg[4];
    #pragma unroll
    for (int j = 0; j < 4; j++) { int L = tid + j * 256; lrow[j] = L >> 3; lcg[j] = L & 7; }

#define G_LOAD(c, st) do { \
    uint32_t _s = sbase + SM_STG + (st) * STG_B; \
    _Pragma("unroll") \
    for (int _j = 0; _j < 4; _j++) { \
        size_t _g = ((size_t)lrow[_j] * 1024 + (size_t)(c) * 64 + lcg[_j] * 8) * 2; \
        uint32_t _d = _s + lrow[_j] * TPITCH + lcg[_j] * 16; \
        CP16(_d + 0*TILE_B, gb0 + _g); \
        CP16(_d + 1*TILE_B, gb1 + _g); \
        CP16(_d + 2*TILE_B, gb2 + _g); \
        CP16(_d + 3*TILE_B, gb3 + _g); \
    } \
    CP_COMMIT(); \
} while(0)

    G_LOAD(0, 0); G_LOAD(1, 1); G_LOAD(2, 2);

    float acc[2][8][4];
    #pragma unroll
    for (int a = 0; a < 2; a++)
        #pragma unroll
        for (int b = 0; b < 8; b++)
            #pragma unroll
            for (int q = 0; q < 4; q++) acc[a][b][q] = 0.f;

    int arow = lane & 15, akb = (lane >> 4) * 16;
    int brow = ((lane >> 4) << 3) + (lane & 7), bkb = ((lane >> 3) & 1) * 16;

    for (int c = 0; c < 16; c++) {
        int st = c % 3;
        if (c <= 13) CP_WAIT(2); else if (c == 14) CP_WAIT(1); else CP_WAIT(0);
        __syncthreads();
        uint32_t sA = sbase + SM_STG + st * STG_B;
        uint32_t sB = sA + 2 * TILE_B;
        #pragma unroll
        for (int ks = 0; ks < 4; ks++) {
            uint32_t ah[2][4], al[2][4];
            #pragma unroll
            for (int mt = 0; mt < 2; mt++) {
                uint32_t ad = sA + (wm * 32 + mt * 16 + arow) * TPITCH + ks * 32 + akb;
                ldsm4(ah[mt], ad);
                ldsm4(al[mt], ad + TILE_B);
            }
            uint32_t bh[16], bl[16];
            #pragma unroll
            for (int p = 0; p < 4; p++) {
                uint32_t bd = sB + (wn * 64 + p * 16 + brow) * TPITCH + ks * 32 + bkb;
                ldsm4(&bh[4 * p], bd);
                ldsm4(&bl[4 * p], bd + TILE_B);
            }
            #pragma unroll
            for (int mt = 0; mt < 2; mt++)
                #pragma unroll
                for (int nt = 0; nt < 8; nt++) {
                    int f = (nt >> 1) * 4 + (nt & 1) * 2;
                    mma_bf16(acc[mt][nt], ah[mt], bh[f], bh[f + 1]);
                    mma_bf16(acc[mt][nt], ah[mt], bl[f], bl[f + 1]);
                    mma_bf16(acc[mt][nt], al[mt], bh[f], bh[f + 1]);
                }
        }
        __syncthreads();
        if (c + 3 < 16) G_LOAD(c + 3, st);
    }

    const float* bms = (const float*)smem;
    #pragma unroll
    for (int mt = 0; mt < 2; mt++) {
        int r0l = wm * 32 + mt * 16 + (lane >> 2);
        const float* lp0 = low + (size_t)(m0 + r0l) * RR;
        const float* lp1 = lp0 + 8 * RR;
        float la0[8], la1[8];
        *(float4*)(la0)     = *(const float4*)(lp0);
        *(float4*)(la0 + 4) = *(const float4*)(lp0 + 4);
        *(float4*)(la1)     = *(const float4*)(lp1);
        *(float4*)(la1 + 4) = *(const float4*)(lp1 + 4);
        #pragma unroll
        for (int nt = 0; nt < 8; nt++) {
            int cl = wn * 64 + nt * 8 + (lane & 3) * 2;
            const float* bp0 = bms + cl * 8;
            const float* bp1 = bp0 + 8;
            float a00 = 0, a01 = 0, a10 = 0, a11 = 0;
            #pragma unroll
            for (int r = 0; r < 8; r++) {
                a00 += la0[r] * bp0[r]; a01 += la0[r] * bp1[r];
                a10 += la1[r] * bp0[r]; a11 += la1[r] * bp1[r];
            }
            float v00 = acc[mt][nt][0] + a00, v01 = acc[mt][nt][1] + a01;
            float v10 = acc[mt][nt][2] + a10, v11 = acc[mt][nt][3] + a11;
            size_t i0 = (size_t)(m0 + r0l) * DIMN + n0 + cl;
            size_t i1 = i0 + (size_t)8 * DIMN;
            if (Cf) {
                *(float2*)(Cf + i0) = make_float2(v00, v01);
                *(float2*)(Cf + i1) = make_float2(v10, v11);
            }
            if (Chi) {
                uint32_t h, l;
                split2(v00, v01, h, l);
                *(uint32_t*)(Chi + i0) = h; *(uint32_t*)(Clo + i0) = l;
                split2(v10, v11, h, l);
                *(uint32_t*)(Chi + i1) = h; *(uint32_t*)(Clo + i1) = l;
            }
        }
    }
}

// ======================= HMMA flash attention ==============================
// BQ=64, BKV=64, DH=64, 4 warps. Stage: KH,KL,VH,VL each 64x(64+8) b16.
#define AST_B 36864          /* 4 * 9216 */
#define ASMEM (2*AST_B)      /* 73728 */

__global__ __launch_bounds__(128)
void attn_mma()
{
    extern __shared__ char smem[];
    uint32_t sbase = smem_u32(smem);
    int tid = threadIdx.x, lane = tid & 31, wid = tid >> 5;
    int qt = blockIdx.x, h = blockIdx.y, b = blockIdx.z;
    int q0 = qt * 64;
    int nkv = ((qt >> 2) + 1) * 4;

    // ---- stage Q hi/lo, build A fragments in registers ----
    #pragma unroll
    for (int j = 0; j < 8; j++) {
        int L = tid + j * 128;
        int t = L >> 9, rr = (L >> 3) & 63, cg = L & 7;
        const __nv_bfloat16* src = (t ? g_qlo : g_qhi)
            + ((size_t)(b * TT + q0 + rr) * INNER + h * 64 + cg * 8);
        CP16(sbase + t * 9216 + rr * TPITCH + cg * 16, src);
    }
    CP_COMMIT(); CP_WAIT(0);
    __syncthreads();
    uint32_t qh[4][4], ql[4][4];
    {
        int arow = lane & 15, akb = (lane >> 4) * 16;
        #pragma unroll
        for (int ks = 0; ks < 4; ks++) {
            uint32_t ad = sbase + (wid * 16 + arow) * TPITCH + ks * 32 + akb;
            ldsm4(qh[ks], ad);
            ldsm4(ql[ks], ad + 9216);
        }
    }
    __syncthreads();

#define KV_LOAD(kb, s) do { \
    _Pragma("unroll") \
    for (int _j = 0; _j < 16; _j++) { \
        int _L = tid + _j * 128; \
        int _t = _L >> 9, _rr = (_L >> 3) & 63, _cg = _L & 7; \
        const __nv_bfloat16* _src = \
            (_t == 0 ? g_khi : _t == 1 ? g_klo : _t == 2 ? g_vhi : g_vlo) \
            + ((size_t)(b * TT + (kb) * 64 + _rr) * INNER + h * 64 + _cg * 8); \
        CP16(sbase + (s) * AST_B + _t * 9216 + _rr * TPITCH + _cg * 16, _src); \
    } \
    CP_COMMIT(); \
} while(0)

    KV_LOAD(0, 0); KV_LOAD(1, 1);

    float oacc[8][4];
    #pragma unroll
    for (int d = 0; d < 8; d++)
        #pragma unroll
        for (int q = 0; q < 4; q++) oacc[d][q] = 0.f;
    float mi0 = -1e30f, mi1 = -1e30f, li0 = 0.f, li1 = 0.f;

    int brow = ((lane >> 4) << 3) + (lane & 7), bkb = ((lane >> 3) & 1) * 16;
    int vrow_b = ((lane >> 3) & 1) * 8 + (lane & 7);
    int vcb = ((lane >> 4) << 3) * 2;

    for (int kb = 0; kb < nkv; kb++) {
        if (kb < nkv - 1) { CP_WAIT(1); } else { CP_WAIT(0); }
        __syncthreads();
        int s = kb & 1;
        uint32_t sK = sbase + s * AST_B;
        uint32_t sV = sK + 18432;

        float sacc[8][4];
        #pragma unroll
        for (int nt = 0; nt < 8; nt++)
            #pragma unroll
            for (int q = 0; q < 4; q++) sacc[nt][q] = 0.f;

        #pragma unroll
        for (int ks = 0; ks < 4; ks++) {
            uint32_t kh[16], kl[16];
            #pragma unroll
            for (int p = 0; p < 4; p++) {
                uint32_t bd = sK + (p * 16 + brow) * TPITCH + ks * 32 + bkb;
                ldsm4(&kh[4 * p], bd);
                ldsm4(&kl[4 * p], bd + 9216);
            }
            #pragma unroll
            for (int nt = 0; nt < 8; nt++) {
                int f = (nt >> 1) * 4 + (nt & 1) * 2;
                mma_bf16(sacc[nt], qh[ks], kh[f], kh[f + 1]);
                mma_bf16(sacc[nt], qh[ks], kl[f], kl[f + 1]);
                mma_bf16(sacc[nt], ql[ks], kh[f], kh[f + 1]);
            }
        }
        // softmax
        float mx0 = -1e30f, mx1 = -1e30f;
        #pragma unroll
        for (int nt = 0; nt < 8; nt++) {
            sacc[nt][0] *= 0.125f; sacc[nt][1] *= 0.125f;
            sacc[nt][2] *= 0.125f; sacc[nt][3] *= 0.125f;
            mx0 = fmaxf(mx0, fmaxf(sacc[nt][0], sacc[nt][1]));
            mx1 = fmaxf(mx1, fmaxf(sacc[nt][2], sacc[nt][3]));
        }
        mx0 = fmaxf(mx0, __shfl_xor_sync(~0u, mx0, 1));
        mx0 = fmaxf(mx0, __shfl_xor_sync(~0u, mx0, 2));
        mx1 = fmaxf(mx1, __shfl_xor_sync(~0u, mx1, 1));
        mx1 = fmaxf(mx1, __shfl_xor_sync(~0u, mx1, 2));
        float mn0 = fmaxf(mi0, mx0), mn1 = fmaxf(mi1, mx1);
        float al0 = __expf(mi0 - mn0), al1 = __expf(mi1 - mn1);
        float rs0 = 0.f, rs1 = 0.f;
        #pragma unroll
        for (int nt = 0; nt < 8; nt++) {
            sacc[nt][0] = __expf(sacc[nt][0] - mn0);
            sacc[nt][1] = __expf(sacc[nt][1] - mn0);
            sacc[nt][2] = __expf(sacc[nt][2] - mn1);
            sacc[nt][3] = __expf(sacc[nt][3] - mn1);
            rs0 += sacc[nt][0] + sacc[nt][1];
            rs1 += sacc[nt][2] + sacc[nt][3];
        }
        rs0 += __shfl_xor_sync(~0u, rs0, 1);
        rs0 += __shfl_xor_sync(~0u, rs0, 2);
        rs1 += __shfl_xor_sync(~0u, rs1, 1);
        rs1 += __shfl_xor_sync(~0u, rs1, 2);
        li0 = li0 * al0 + rs0; li1 = li1 * al1 + rs1;
        mi0 = mn0; mi1 = mn1;
        #pragma unroll
        for (int d = 0; d < 8; d++) {
            oacc[d][0] *= al0; oacc[d][1] *= al0;
            oacc[d][2] *= al1; oacc[d][3] *= al1;
        }
        // P @ V
        #pragma unroll
        for (int j = 0; j < 4; j++) {
            uint32_t ph[4], pl[4];
            split2(sacc[2*j][0],   sacc[2*j][1],   ph[0], pl[0]);
            split2(sacc[2*j][2],   sacc[2*j][3],   ph[1], pl[1]);
            split2(sacc[2*j+1][0], sacc[2*j+1][1], ph[2], pl[2]);
            split2(sacc[2*j+1][2], sacc[2*j+1][3], ph[3], pl[3]);
            uint32_t vh[16], vl[16];
            #pragma unroll
            for (int p = 0; p < 4; p++) {
                uint32_t vd = sV + (16 * j + vrow_b) * TPITCH + p * 32 + vcb;
                ldsm4t(&vh[4 * p], vd);
                ldsm4t(&vl[4 * p], vd + 9216);
            }
            #pragma unroll
            for (int dt = 0; dt < 8; dt++) {
                int f = (dt >> 1) * 4 + (dt & 1) * 2;
                mma_bf16(oacc[dt], ph, vh[f], vh[f + 1]);
                mma_bf16(oacc[dt], ph, vl[f], vl[f + 1]);
                mma_bf16(oacc[dt], pl, vh[f], vh[f + 1]);
            }
        }
        __syncthreads();
        if (kb + 2 < nkv) KV_LOAD(kb + 2, s);
    }

    // ---- write out ----
    int r0l = wid * 16 + (lane >> 2);
    size_t row0 = (size_t)(b * TT + q0 + r0l);
    size_t row1 = row0 + 8;
    float inv0 = 1.f / li0, inv1 = 1.f / li1;
    #pragma unroll
    for (int dt = 0; dt < 8; dt++) {
        int d = h * 64 + dt * 8 + (lane & 3) * 2;
        float v00 = oacc[dt][0] * inv0, v01 = oacc[dt][1] * inv0;
        float v10 = oacc[dt][2] * inv1, v11 = oacc[dt][3] * inv1;
        *(float2*)(g_ao + row0 * INNER + d) = make_float2(v00, v01);
        *(float2*)(g_ao + row1 * INNER + d) = make_float2(v10, v11);
        uint32_t hh, ll;
        split2(v00, v01, hh, ll);
        *(uint32_t*)(g_aohi + row0 * INNER + d) = hh;
        *(uint32_t*)(g_aolo + row0 * INNER + d) = ll;
        split2(v10, v11, hh, ll);
        *(uint32_t*)(g_aohi + row1 * INNER + d) = hh;
        *(uint32_t*)(g_aolo + row1 * INNER + d) = ll;
    }
}

// ---------------- LayerNorm (+ x hi/lo split) ------------------------------
__global__ void ln_kernel(const float* __restrict__ x, const float* __restrict__ mt,
                          const float* __restrict__ gx, const float* __restrict__ bx,
                          const float* __restrict__ gm, const float* __restrict__ bm)
{
    int t = blockIdx.x;
    int which = blockIdx.y;
    const float* src = (which ? mt : x) + (size_t)t * DIMN;
    float*       dst = (which ? g_mn : g_xn) + (size_t)t * DIMN;
    const float* g = which ? gm : gx;
    const float* b = which ? bm : bx;
    int tid = threadIdx.x;
    float4 v = ((const float4*)src)[tid];
    float s  = v.x + v.y + v.z + v.w;
    float sq = v.x*v.x + v.y*v.y + v.z*v.z + v.w*v.w;
    __shared__ float red[2][8];
    #pragma unroll
    for (int m = 16; m; m >>= 1) {
        s  += __shfl_xor_sync(~0u, s, m);
        sq += __shfl_xor_sync(~0u, sq, m);
    }
    int w = tid >> 5, l = tid & 31;
    if (l == 0) { red[0][w] = s; red[1][w] = sq; }
    __syncthreads();
    if (w == 0) {
        float s2 = (l < 8) ? red[0][l] : 0.f;
        float q2 = (l < 8) ? red[1][l] : 0.f;
        #pragma unroll
        for (int m = 4; m; m >>= 1) {
            s2 += __shfl_xor_sync(~0u, s2, m);
            q2 += __shfl_xor_sync(~0u, q2, m);
        }
        if (l == 0) { red[0][0] = s2; red[1][0] = q2; }
    }
    __syncthreads();
    s = red[0][0]; sq = red[1][0];
    float mean = s * (1.f / DIMN);
    float var  = sq * (1.f / DIMN) - mean * mean;
    float rstd = rsqrtf(var + EPS_LN);
    float4 gv = ((const float4*)g)[tid];
    float4 bv = ((const float4*)b)[tid];
    float4 o;
    o.x = (v.x - mean) * rstd * gv.x + bv.x;
    o.y = (v.y - mean) * rstd * gv.y + bv.y;
    o.z = (v.z - mean) * rstd * gv.z + bv.z;
    o.w = (v.w - mean) * rstd * gv.w + bv.w;
    ((float4*)dst)[tid] = o;
    if (which == 0) {
        uint32_t h0, l0, h1, l1;
        split2(o.x, o.y, h0, l0);
        split2(o.z, o.w, h1, l1);
        ((uint2*)(g_xhi + (size_t)t * DIMN))[tid] = make_uint2(h0, h1);
        ((uint2*)(g_xlo + (size_t)t * DIMN))[tid] = make_uint2(l0, l1);
    }
}

// ---------------- per-token rank-8 dots ------------------------------------
__global__ void dots_kernel(const float* __restrict__ Gq, const float* __restrict__ Gk,
                            const float* __restrict__ Gv, const float* __restrict__ Go,
                            const float* __restrict__ Aq, const float* __restrict__ Ak,
                            const float* __restrict__ Av)
{
    int tid = threadIdx.x;
    int w = tid >> 5, lane = tid & 31;
    int tok = blockIdx.x * 8 + w;
    const float4* x4 = (const float4*)(g_xn + (size_t)tok * DIMN);
    const float4* m4 = (const float4*)(g_mn + (size_t)tok * DIMN);
    __shared__ float stage[8][56];
    for (int o = 0; o < 56; o++) {
        const float4* w4;
        const float4* s4;
        if (o < 32) {
            int p = o >> 3, r = o & 7;
            const float* G = (p == 0) ? Gq : (p == 1) ? Gk : (p == 2) ? Gv : Go;
            w4 = (const float4*)(G + (size_t)r * DIMN);
            s4 = m4;
        } else {
            int oo = o - 32; int p = oo >> 3, r = oo & 7;
            const float* A = (p == 0) ? Aq : (p == 1) ? Ak : Av;
            w4 = (const float4*)(A + (size_t)r * DIMN);
            s4 = x4;
        }
        float acc = 0.f;
        #pragma unroll
        for (int k = lane; k < DIMN / 4; k += 32) {
            float4 a = s4[k], c = w4[k];
            acc += a.x*c.x + a.y*c.y + a.z*c.z + a.w*c.w;
        }
        #pragma unroll
        for (int m = 16; m; m >>= 1) acc += __shfl_xor_sync(~0u, acc, m);
        if (lane == 0) stage[w][o] = acc;
    }
    __syncwarp();
    if (lane < 8) {
        int r = lane;
        g_gateo[(size_t)tok * RR + r] = stage[w][24 + r];
        #pragma unroll
        for (int p = 0; p < 3; p++) {
            float gate = stage[w][p * 8 + r];
            float lowr = stage[w][32 + p * 8 + r];
            g_low[((size_t)p * NT + tok) * RR + r] = lowr * gate * LORA_SCALE;
        }
    }
}

// ---------------- rank-8 dots for output projection ------------------------
__global__ void lowo_kernel(const float* __restrict__ Ao)
{
    int tid = threadIdx.x;
    int w = tid >> 5, lane = tid & 31;
    int tok = blockIdx.x * 8 + w;
    const float4* a4 = (const float4*)(g_ao + (size_t)tok * INNER);
    for (int r = 0; r < RR; r++) {
        const float4* w4 = (const float4*)(Ao + (size_t)r * INNER);
        float acc = 0.f;
        #pragma unroll
        for (int k = lane; k < INNER / 4; k += 32) {
            float4 a = a4[k], c = w4[k];
            acc += a.x*c.x + a.y*c.y + a.z*c.z + a.w*c.w;
        }
        #pragma unroll
        for (int m = 16; m; m >>= 1) acc += __shfl_xor_sync(~0u, acc, m);
        if (lane == 0)
            g_lowo[(size_t)tok * RR + r] = acc * g_gateo[(size_t)tok * RR + r] * LORA_SCALE;
    }
}

// ---------------- launch ---------------------------------------------------
extern "C" void kernel_launch(void* const* d_in, const int* in_sizes, int n_in,
                              void* d_out, int out_size)
{
    const float* x  = (const float*)d_in[0];
    const float* mt = (const float*)d_in[1];
    const float* ng = (const float*)d_in[2];
    const float* nb = (const float*)d_in[3];
    const float* mg = (const float*)d_in[4];
    const float* mb = (const float*)d_in[5];
    const float* Wq = (const float*)d_in[6];
    const float* Aq = (const float*)d_in[7];
    const float* Bq = (const float*)d_in[8];
    const float* Gq = (const float*)d_in[9];
    const float* Wk = (const float*)d_in[10];
    const float* Ak = (const float*)d_in[11];
    const float* Bk = (const float*)d_in[12];
    const float* Gk = (const float*)d_in[13];
    const float* Wv = (const float*)d_in[14];
    const float* Av = (const float*)d_in[15];
    const float* Bv = (const float*)d_in[16];
    const float* Gv = (const float*)d_in[17];
    const float* Wo = (const float*)d_in[18];
    const float* Ao = (const float*)d_in[19];
    const float* Bo = (const float*)d_in[20];
    const float* Go = (const float*)d_in[21];
    float* out = (float*)d_out;

    float *lowb, *lowob;
    __nv_bfloat16 *xhi, *xlo, *whi, *wlo, *qhi, *qlo, *khi, *klo, *vhi, *vlo, *aohi, *aolo;
    cudaGetSymbolAddress((void**)&lowb,  g_low);
    cudaGetSymbolAddress((void**)&lowob, g_lowo);
    cudaGetSymbolAddress((void**)&xhi,   g_xhi);
    cudaGetSymbolAddress((void**)&xlo,   g_xlo);
    cudaGetSymbolAddress((void**)&whi,   g_whi);
    cudaGetSymbolAddress((void**)&wlo,   g_wlo);
    cudaGetSymbolAddress((void**)&qhi,   g_qhi);
    cudaGetSymbolAddress((void**)&qlo,   g_qlo);
    cudaGetSymbolAddress((void**)&khi,   g_khi);
    cudaGetSymbolAddress((void**)&klo,   g_klo);
    cudaGetSymbolAddress((void**)&vhi,   g_vhi);
    cudaGetSymbolAddress((void**)&vlo,   g_vlo);
    cudaGetSymbolAddress((void**)&aohi,  g_aohi);
    cudaGetSymbolAddress((void**)&aolo,  g_aolo);

    cudaFuncSetAttribute(gemm_mma, cudaFuncAttributeMaxDynamicSharedMemorySize, GSMEM);
    cudaFuncSetAttribute(attn_mma, cudaFuncAttributeMaxDynamicSharedMemorySize, ASMEM);

    const int n4w = DIMN * INNER / 4;

    ln_kernel<<<dim3(NT, 2), 256>>>(x, mt, ng, nb, mg, mb);
    dots_kernel<<<NT / 8, 256>>>(Gq, Gk, Gv, Go, Aq, Ak, Av);

    cvt_split<<<(n4w + 255) / 256, 256>>>((const float4*)Wq, (uint2*)whi, (uint2*)wlo, n4w);
    gemm_mma<<<dim3(8, 32), 256, GSMEM>>>(xhi, xlo, whi, wlo,
        lowb + 0 * (size_t)NT * RR, Bq, qhi, qlo, nullptr);
    cvt_split<<<(n4w + 255) / 256, 256>>>((const float4*)Wk, (uint2*)whi, (uint2*)wlo, n4w);
    gemm_mma<<<dim3(8, 32), 256, GSMEM>>>(xhi, xlo, whi, wlo,
        lowb + 1 * (size_t)NT * RR, Bk, khi, klo, nullptr);
    cvt_split<<<(n4w + 255) / 256, 256>>>((const float4*)Wv, (uint2*)whi, (uint2*)wlo, n4w);
    gemm_mma<<<dim3(8, 32), 256, GSMEM>>>(xhi, xlo, whi, wlo,
        lowb + 2 * (size_t)NT * RR, Bv, vhi, vlo, nullptr);

    attn_mma<<<dim3(32, HEADS, BB), 128, ASMEM>>>();
    lowo_kernel<<<NT / 8, 256>>>(Ao);

    cvt_split<<<(n4w + 255) / 256, 256>>>((const float4*)Wo, (uint2*)whi, (uint2*)wlo, n4w);
    gemm_mma<<<dim3(8, 32), 256, GSMEM>>>(aohi, aolo, whi, wlo,
        lowob, Bo, nullptr, nullptr, out);
}